// round 15
// baseline (speedup 1.0000x reference)
#include <cuda_runtime.h>

// SpMM: y = x @ W^T, W CSR, uniform 128 nnz/row, indices SORTED per row.
//   x [512,2048] f32, data [262144] f32, indices [262144] i32,
//   indptr [2049] i32, y [512,2048] f32.
//
// R14 = R13 with the record-addressing bug fixed: records are laid out by
// row-WITHIN-GROUP (stride 32B inside a 256B chunk record); main must index
// with (tid>>3)&3, not the block-level row_sub. R13 used row_sub -> OOB.
//
// Plan recap:
//   PREP (~4us): per 4-row group x column-half, binary-search the half
//   split, emit padded 8-nnz chunk records: 256B = 32 w floats
//   [row_in_grp*8+j] + 32 precomputed smem byte-offsets pk = 144*(col&1023).
//   Out-of-segment slots: w=0, pk=0. Per-nnz masking/address math paid once.
//   MAIN: CH=32 tokens/block; x staged in two 1024-col halves, PADDED layout
//   (column c at word 36c -> conflict-free stores AND gathers, no swizzle).
//   Inner loop per nnz-j: IADD + LDS.128 + 4 FFMA. Records are 1-line
//   broadcast LDG.128s, double-buffered with clamped prefetch.

#define NTOK    512
#define NIN     2048
#define NOUT    2048
#define CH      32                    // tokens per block
#define HALF    1024                  // cols per staged half
#define RPB     128                   // rows per block
#define THREADS 1024
#define MAXT    16                    // max 8-nnz chunks per (row, half)
#define NGRP    (NOUT / 4)            // 512 groups of 4 rows
#define COLPAD  36                    // words per column: 32 data + 4 pad
#define SMEM_WORDS (HALF * COLPAD)    // 36864 words = 147456 B

// chunk record: 256B = w floats (lane = row_in_grp*8 + j) then pk ints
__device__ __align__(256) uint4 g_rec[(size_t)NGRP * 2 * MAXT * 16];  // 4 MB
__device__ int g_trips[NGRP * 2];

// ---------------------------------------------------------------------------
__global__ void prep_kernel(const float* __restrict__ data,
                            const int*   __restrict__ indices,
                            const int*   __restrict__ indptr)
{
    const int wid  = blockIdx.x * (blockDim.x >> 5) + (threadIdx.x >> 5);
    const int lane = threadIdx.x & 31;
    const int g = wid >> 1;           // 4-row group
    const int h = wid & 1;            // column half
    const int r = g * 4 + (lane >> 3);
    const int j = lane & 7;

    const int base = __ldg(&indptr[r]);
    const int kend = __ldg(&indptr[r + 1]);

    // first k with col >= HALF (indices sorted per row)
    int lo = base, hi = kend;
    while (lo < hi) {
        const int mid = (lo + hi) >> 1;
        if (__ldg(&indices[mid]) < HALF) lo = mid + 1; else hi = mid;
    }
    const int s = h ? lo : base;
    const int e = h ? kend : lo;

    int mt = (e - s + 7) >> 3;        // this row's chunk count
    mt = max(mt, __shfl_xor_sync(0xffffffffu, mt, 8));
    mt = max(mt, __shfl_xor_sync(0xffffffffu, mt, 16));
    if (lane == 0) g_trips[g * 2 + h] = mt;

    float* rec = (float*)(g_rec + (size_t)(g * 2 + h) * MAXT * 16);
    for (int t = 0; t < mt; ++t) {
        const int  kk = s + t * 8 + j;
        const bool ok = kk < e;
        const float wv = ok ? __ldg(&data[kk]) : 0.f;
        const int   cl = ok ? (__ldg(&indices[kk]) & (HALF - 1)) : 0;
        float* rf = rec + t * 64;
        rf[lane] = wv;                               // w
        ((int*)rf)[32 + lane] = cl * (COLPAD * 4);   // precomputed byte offset
    }
}

// ---------------------------------------------------------------------------
__global__ void __launch_bounds__(THREADS, 1)
spmm_main(const float* __restrict__ x, float* __restrict__ y)
{
    extern __shared__ float s_x[];

    const int tid  = threadIdx.x;
    const int lane = tid & 31;
    const int o    = lane & 7;            // token-octet (4 tokens)
    const int rg   = (tid >> 3) & 3;      // row WITHIN 4-row group  (R14 fix)
    const int row  = blockIdx.x * RPB + (tid >> 3);
    const int tok0 = blockIdx.y * CH;
    const int g    = blockIdx.x * (RPB / 4) + (tid >> 5);  // warp's group

    const char* tb = (const char*)s_x + o * 16;   // thread's smem base

    float4 acc = make_float4(0.f, 0.f, 0.f, 0.f);

    #pragma unroll
    for (int h = 0; h < 2; ++h) {
        __syncthreads();                  // previous half's readers done
        // ---------------- stage half h (padded, conflict-free) ----------
        {
            const int gc0 = h * HALF;
            #pragma unroll
            for (int q = 0; q < 8; ++q) {     // token quad q, col = tid
                const float* xp = x + (size_t)(tok0 + (q << 2)) * NIN + gc0 + tid;
                float4 v;
                v.x = __ldg(xp);
                v.y = __ldg(xp + NIN);
                v.z = __ldg(xp + 2 * NIN);
                v.w = __ldg(xp + 3 * NIN);
                *reinterpret_cast<float4*>(s_x + tid * COLPAD + q * 4) = v;
            }
        }
        __syncthreads();

        // ---------------- consume precomputed chunk records --------------
        const int mt = g_trips[g * 2 + h];
        const char* rc = (const char*)(g_rec + (size_t)(g * 2 + h) * MAXT * 16)
                       + rg * 32;         // row-in-group stride (R14 fix)

        float4 wa, wb; int4 pa, pb;
        if (mt > 0) {
            wa = *(const float4*)(rc);
            wb = *(const float4*)(rc + 16);
            pa = *(const int4*)(rc + 128);
            pb = *(const int4*)(rc + 144);
        }
        for (int t = 0; t < mt; ++t) {
            // branch-free clamped prefetch of next chunk (always in-bounds)
            const char* rn = rc + (size_t)min(t + 1, mt - 1) * 256;
            const float4 nwa = *(const float4*)(rn);
            const float4 nwb = *(const float4*)(rn + 16);
            const int4   npa = *(const int4*)(rn + 128);
            const int4   npb = *(const int4*)(rn + 144);

            float4 v;
            v = *(const float4*)(tb + pa.x);
            acc.x = fmaf(wa.x, v.x, acc.x); acc.y = fmaf(wa.x, v.y, acc.y);
            acc.z = fmaf(wa.x, v.z, acc.z); acc.w = fmaf(wa.x, v.w, acc.w);
            v = *(const float4*)(tb + pa.y);
            acc.x = fmaf(wa.y, v.x, acc.x); acc.y = fmaf(wa.y, v.y, acc.y);
            acc.z = fmaf(wa.y, v.z, acc.z); acc.w = fmaf(wa.y, v.w, acc.w);
            v = *(const float4*)(tb + pa.z);
            acc.x = fmaf(wa.z, v.x, acc.x); acc.y = fmaf(wa.z, v.y, acc.y);
            acc.z = fmaf(wa.z, v.z, acc.z); acc.w = fmaf(wa.z, v.w, acc.w);
            v = *(const float4*)(tb + pa.w);
            acc.x = fmaf(wa.w, v.x, acc.x); acc.y = fmaf(wa.w, v.y, acc.y);
            acc.z = fmaf(wa.w, v.z, acc.z); acc.w = fmaf(wa.w, v.w, acc.w);
            v = *(const float4*)(tb + pb.x);
            acc.x = fmaf(wb.x, v.x, acc.x); acc.y = fmaf(wb.x, v.y, acc.y);
            acc.z = fmaf(wb.x, v.z, acc.z); acc.w = fmaf(wb.x, v.w, acc.w);
            v = *(const float4*)(tb + pb.y);
            acc.x = fmaf(wb.y, v.x, acc.x); acc.y = fmaf(wb.y, v.y, acc.y);
            acc.z = fmaf(wb.y, v.z, acc.z); acc.w = fmaf(wb.y, v.w, acc.w);
            v = *(const float4*)(tb + pb.z);
            acc.x = fmaf(wb.z, v.x, acc.x); acc.y = fmaf(wb.z, v.y, acc.y);
            acc.z = fmaf(wb.z, v.z, acc.z); acc.w = fmaf(wb.z, v.w, acc.w);
            v = *(const float4*)(tb + pb.w);
            acc.x = fmaf(wb.w, v.x, acc.x); acc.y = fmaf(wb.w, v.y, acc.y);
            acc.z = fmaf(wb.w, v.z, acc.z); acc.w = fmaf(wb.w, v.w, acc.w);

            wa = nwa; wb = nwb; pa = npa; pb = npb;
        }
    }

    // ---------------- writeback: y[tok][row], tokens tok0+4o+{0..3} --------
    float* yp = y + (size_t)(tok0 + (o << 2)) * NOUT + row;
    yp[0]                = acc.x;
    yp[NOUT]             = acc.y;
    yp[2 * (size_t)NOUT] = acc.z;
    yp[3 * (size_t)NOUT] = acc.w;
}

// ---------------------------------------------------------------------------
extern "C" void kernel_launch(void* const* d_in, const int* in_sizes, int n_in,
                              void* d_out, int out_size)
{
    const float* x       = (const float*)d_in[0];
    const float* data    = (const float*)d_in[1];
    const int*   indices = (const int*)d_in[2];
    const int*   indptr  = (const int*)d_in[3];
    float*       y       = (float*)d_out;

    cudaFuncSetAttribute(spmm_main,
                         cudaFuncAttributeMaxDynamicSharedMemorySize,
                         SMEM_WORDS * (int)sizeof(float));

    // 1024 warps = NGRP*2 (one per group-half)
    prep_kernel<<<128, 256>>>(data, indices, indptr);

    dim3 grid(NOUT / RPB, NTOK / CH);   // (16, 16) = 256 blocks
    spmm_main<<<grid, THREADS, SMEM_WORDS * sizeof(float)>>>(x, y);
}